// round 6
// baseline (speedup 1.0000x reference)
#include <cuda_runtime.h>
#include <cuda_bf16.h>
#include <math.h>
#include <stdint.h>

// ---------------------------------------------------------------------------
// Problem constants
// ---------------------------------------------------------------------------
#define NB   4        // batch
#define NT   1024     // time steps
#define NL   512      // latent / emb
#define NV   50257    // vocab
#define NR   (NB*NT)  // 4096 rows
#define NVP  50304    // padded vocab pitch (= 393*128, 16B-aligned rows)

// small GEMM tiling (register-staged)
#define BM   256
#define BN   128
#define BK   16
#define GT   512
#define GEMM_SMEM ((2*BM*20 + 2*BK*136)*4)

// big GEMM tiling (cp.async pipelined)
#define UBM 128
#define UBN 128
#define UBK 16
#define UST 4
#define UAS (UBM*20)
#define UBS (UBK*132)
#define UGEMM_SMEM (UST*(UAS+UBS)*4)

// ---------------------------------------------------------------------------
// Scratch (device globals — no allocation allowed)
// ---------------------------------------------------------------------------
__device__ float g_bufA[NR * NL];     // XW0 (= embed[x]@Wx0 + b0)
__device__ float g_bufB[NR * NL];     // H1, stored tf32-rounded
__device__ float g_wu[NL * NVP];      // Wu, tf32-rounded + padded
__device__ float4 g_h0[4][NL];        // depth-4 ring, layer-0 h, [k]={b0..b3}
__device__ float4 g_h1[4][NL];        // depth-4 ring, layer-1 h
__device__ unsigned g_bars[64];       // [0]=bar0 (layer0), [32]=bar1 (layer1)

// ---------------------------------------------------------------------------
// Helpers
// ---------------------------------------------------------------------------
__device__ __forceinline__ unsigned f2tf32(float f) {
    unsigned u;
    asm("cvt.rna.tf32.f32 %0, %1;" : "=r"(u) : "f"(f));
    return u;
}

__device__ __forceinline__ void mma_tf32(float c[4], const unsigned a[4],
                                         const unsigned b[2]) {
    asm volatile(
        "mma.sync.aligned.m16n8k8.row.col.f32.tf32.tf32.f32 "
        "{%0,%1,%2,%3},{%4,%5,%6,%7},{%8,%9},{%0,%1,%2,%3};"
        : "+f"(c[0]), "+f"(c[1]), "+f"(c[2]), "+f"(c[3])
        : "r"(a[0]), "r"(a[1]), "r"(a[2]), "r"(a[3]), "r"(b[0]), "r"(b[1]));
}

__device__ __forceinline__ void cp16(uint32_t dst, const void* src) {
    asm volatile("cp.async.cg.shared.global [%0], [%1], 16;\n"
                 :: "r"(dst), "l"(src));
}

__device__ __forceinline__ void wait_ge(const unsigned* p, unsigned tgt) {
    if (tgt == 0u) return;
    unsigned v;
    do {
        asm volatile("ld.acquire.gpu.global.u32 %0, [%1];"
                     : "=r"(v) : "l"(p) : "memory");
    } while (v < tgt);
}

// ---------------------------------------------------------------------------
// init: reset barriers + zero both h rings
// ---------------------------------------------------------------------------
__global__ void init_kernel() {
    const int tid = threadIdx.x;
    if (tid == 0) { g_bars[0] = 0u; g_bars[32] = 0u; }
    float4 z = make_float4(0.f, 0.f, 0.f, 0.f);
    for (int i = tid; i < 4 * NL; i += 256) {
        ((float4*)g_h0)[i] = z;
        ((float4*)g_h1)[i] = z;
    }
}

// ---------------------------------------------------------------------------
// Wu prep: g_wu[k][n] = tf32_rna(Wu[k][n]), zero-padded to pitch NVP
// ---------------------------------------------------------------------------
__global__ void wu_prep(const float* __restrict__ Wu) {
    const int n = blockIdx.x * 256 + threadIdx.x;
    const int k = blockIdx.y;
    if (n < NVP)
        g_wu[(size_t)k * NVP + n] =
            (n < NV) ? __uint_as_float(f2tf32(Wu[(size_t)k * NV + n])) : 0.f;
}

// ---------------------------------------------------------------------------
// Small GEMM: C = A(gathered) @ B + bias (in-loop tf32 cvt). XW0 only.
// ---------------------------------------------------------------------------
__global__ __launch_bounds__(GT, 1)
void gemm_tf32(const float* __restrict__ A, const int* __restrict__ gidx,
               const float* __restrict__ B, const float* __restrict__ bias,
               float* __restrict__ C, int N) {
    extern __shared__ float sm[];
    float* As = sm;
    float* Bs = sm + 2 * BM * 20;

    const int tid  = threadIdx.x;
    const int lane = tid & 31;
    const int warp = tid >> 5;
    const int wm = warp & 3;
    const int wn = warp >> 2;
    const int g  = lane >> 2;
    const int t4 = lane & 3;

    const int rowBase = blockIdx.y * BM;
    const int nb      = blockIdx.x * BN;

    float acc[4][4][4];
#pragma unroll
    for (int a = 0; a < 4; ++a)
#pragma unroll
        for (int b = 0; b < 4; ++b)
#pragma unroll
            for (int e = 0; e < 4; ++e) acc[a][b][e] = 0.f;

    const int rl0 = tid >> 2;
    const int rl1 = rl0 + 128;
    const int c4  = tid & 3;
    const float* arow0;
    const float* arow1;
    {
        const int r0 = rowBase + rl0;
        const int r1 = rowBase + rl1;
        arow0 = A + (size_t)(gidx ? gidx[r0] : r0) * NL;
        arow1 = A + (size_t)(gidx ? gidx[r1] : r1) * NL;
    }

    float4 pa0, pa1;
    float  pb[4];
    pa0 = *(const float4*)(arow0 + c4 * 4);
    pa1 = *(const float4*)(arow1 + c4 * 4);
#pragma unroll
    for (int i = 0; i < 4; ++i) {
        const int id  = tid + i * GT;
        const int kr  = id >> 7;
        const int col = id & 127;
        const int n   = nb + col;
        pb[i] = (n < N) ? B[(size_t)kr * N + n] : 0.f;
    }

    int w = 0;
    for (int kb = 0; kb < NL; kb += BK) {
        {
            float4 w0, w1;
            w0.x = __uint_as_float(f2tf32(pa0.x));
            w0.y = __uint_as_float(f2tf32(pa0.y));
            w0.z = __uint_as_float(f2tf32(pa0.z));
            w0.w = __uint_as_float(f2tf32(pa0.w));
            w1.x = __uint_as_float(f2tf32(pa1.x));
            w1.y = __uint_as_float(f2tf32(pa1.y));
            w1.z = __uint_as_float(f2tf32(pa1.z));
            w1.w = __uint_as_float(f2tf32(pa1.w));
            *(float4*)&As[w * (BM * 20) + rl0 * 20 + c4 * 4] = w0;
            *(float4*)&As[w * (BM * 20) + rl1 * 20 + c4 * 4] = w1;
#pragma unroll
            for (int i = 0; i < 4; ++i) {
                const int id  = tid + i * GT;
                const int kr  = id >> 7;
                const int col = id & 127;
                Bs[w * (BK * 136) + kr * 136 + col] =
                    __uint_as_float(f2tf32(pb[i]));
            }
        }
        __syncthreads();

        if (kb + BK < NL) {
            pa0 = *(const float4*)(arow0 + kb + BK + c4 * 4);
            pa1 = *(const float4*)(arow1 + kb + BK + c4 * 4);
#pragma unroll
            for (int i = 0; i < 4; ++i) {
                const int id  = tid + i * GT;
                const int kr  = id >> 7;
                const int col = id & 127;
                const int n   = nb + col;
                pb[i] = (n < N) ? B[(size_t)(kb + BK + kr) * N + n] : 0.f;
            }
        }

        const float* Aw = &As[w * (BM * 20)];
        const float* Bw = &Bs[w * (BK * 136)];
#pragma unroll
        for (int ks = 0; ks < BK; ks += 8) {
            unsigned af[4][4], bf[4][2];
#pragma unroll
            for (int im = 0; im < 4; ++im) {
                const int m0 = wm * 64 + im * 16;
                const float* a0 = Aw + (m0 + g) * 20 + ks + t4;
                const float* a1 = Aw + (m0 + g + 8) * 20 + ks + t4;
                af[im][0] = __float_as_uint(a0[0]);
                af[im][1] = __float_as_uint(a1[0]);
                af[im][2] = __float_as_uint(a0[4]);
                af[im][3] = __float_as_uint(a1[4]);
            }
#pragma unroll
            for (int in = 0; in < 4; ++in) {
                const int n0 = wn * 32 + in * 8;
                bf[in][0] = __float_as_uint(Bw[(ks + t4) * 136 + n0 + g]);
                bf[in][1] = __float_as_uint(Bw[(ks + t4 + 4) * 136 + n0 + g]);
            }
#pragma unroll
            for (int im = 0; im < 4; ++im)
#pragma unroll
                for (int in = 0; in < 4; ++in)
                    mma_tf32(acc[im][in], af[im], bf[in]);
        }
        w ^= 1;
    }

#pragma unroll
    for (int im = 0; im < 4; ++im) {
        const int r0 = rowBase + wm * 64 + im * 16 + g;
#pragma unroll
        for (int in = 0; in < 4; ++in) {
            const int c0 = nb + wn * 32 + in * 8 + t4 * 2;
#pragma unroll
            for (int e = 0; e < 4; ++e) {
                const int row = r0 + ((e & 2) ? 8 : 0);
                const int col = c0 + (e & 1);
                if (col < N)
                    C[(size_t)row * N + col] = acc[im][in][e] + bias[col];
            }
        }
    }
}

// ---------------------------------------------------------------------------
// Big unembed GEMM: out = H1(tf32 bits) @ g_wu + bu. 128x128x16, cp.async x4.
// ---------------------------------------------------------------------------
__global__ __launch_bounds__(256, 2)
void gemm_unembed(const float* __restrict__ A, const float* __restrict__ bias,
                  float* __restrict__ C) {
    extern __shared__ float sm[];
    const uint32_t smem_u32 = (uint32_t)__cvta_generic_to_shared(sm);

    const int tid  = threadIdx.x;
    const int lane = tid & 31;
    const int warp = tid >> 5;
    const int wm = warp & 1;
    const int wn = warp >> 1;
    const int g  = lane >> 2;
    const int t4 = lane & 3;

    const int rowBase = blockIdx.y * UBM;
    const int nb      = blockIdx.x * UBN;

    float acc[4][4][4];
#pragma unroll
    for (int a = 0; a < 4; ++a)
#pragma unroll
        for (int b = 0; b < 4; ++b)
#pragma unroll
            for (int e = 0; e < 4; ++e) acc[a][b][e] = 0.f;

    const int arow = tid >> 2;
    const int ac4  = tid & 3;
    const float* aptr0 = A + (size_t)(rowBase + arow) * NL + ac4 * 4;
    const float* aptr1 = A + (size_t)(rowBase + arow + 64) * NL + ac4 * 4;
    const int bkr0 = tid >> 5;
    const int bc0  = tid & 31;
    const float* bptr0 = g_wu + (size_t)bkr0 * NVP + nb + bc0 * 4;
    const float* bptr1 = g_wu + (size_t)(bkr0 + 8) * NVP + nb + bc0 * 4;

    const uint32_t adst0 = smem_u32 + (arow * 20 + ac4 * 4) * 4;
    const uint32_t adst1 = smem_u32 + ((arow + 64) * 20 + ac4 * 4) * 4;
    const uint32_t bdst0 = smem_u32 + (UST * UAS + bkr0 * 132 + bc0 * 4) * 4;
    const uint32_t bdst1 = smem_u32 + (UST * UAS + (bkr0 + 8) * 132 + bc0 * 4) * 4;

    const int NKT = NL / UBK;

#pragma unroll
    for (int s = 0; s < UST - 1; ++s) {
        const int kb = s * UBK;
        cp16(adst0 + s * UAS * 4, aptr0 + kb);
        cp16(adst1 + s * UAS * 4, aptr1 + kb);
        cp16(bdst0 + s * UBS * 4, bptr0 + (size_t)kb * NVP);
        cp16(bdst1 + s * UBS * 4, bptr1 + (size_t)kb * NVP);
        asm volatile("cp.async.commit_group;\n" ::);
    }

    for (int kt = 0; kt < NKT; ++kt) {
        asm volatile("cp.async.wait_group 2;\n" ::);
        __syncthreads();

        if (kt + UST - 1 < NKT) {
            const int s  = (kt + UST - 1) & (UST - 1);
            const int kb = (kt + UST - 1) * UBK;
            cp16(adst0 + s * UAS * 4, aptr0 + kb);
            cp16(adst1 + s * UAS * 4, aptr1 + kb);
            cp16(bdst0 + s * UBS * 4, bptr0 + (size_t)kb * NVP);
            cp16(bdst1 + s * UBS * 4, bptr1 + (size_t)kb * NVP);
        }
        asm volatile("cp.async.commit_group;\n" ::);

        const float* Aw = sm + (kt & (UST - 1)) * UAS;
        const float* Bw = sm + UST * UAS + (kt & (UST - 1)) * UBS;
#pragma unroll
        for (int ks = 0; ks < UBK; ks += 8) {
            unsigned af[4][4], bf[4][2];
#pragma unroll
            for (int im = 0; im < 4; ++im) {
                const int m0 = wm * 64 + im * 16;
                const float* a0 = Aw + (m0 + g) * 20 + ks + t4;
                const float* a1 = Aw + (m0 + g + 8) * 20 + ks + t4;
                af[im][0] = __float_as_uint(a0[0]);
                af[im][1] = __float_as_uint(a1[0]);
                af[im][2] = __float_as_uint(a0[4]);
                af[im][3] = __float_as_uint(a1[4]);
            }
#pragma unroll
            for (int in = 0; in < 4; ++in) {
                const int n0 = wn * 32 + in * 8;
                bf[in][0] = __float_as_uint(Bw[(ks + t4) * 132 + n0 + g]);
                bf[in][1] = __float_as_uint(Bw[(ks + t4 + 4) * 132 + n0 + g]);
            }
#pragma unroll
            for (int im = 0; im < 4; ++im)
#pragma unroll
                for (int in = 0; in < 4; ++in)
                    mma_tf32(acc[im][in], af[im], bf[in]);
        }
    }

#pragma unroll
    for (int im = 0; im < 4; ++im) {
        const int r0 = rowBase + wm * 64 + im * 16 + g;
#pragma unroll
        for (int in = 0; in < 4; ++in) {
            const int c0 = nb + wn * 32 + in * 8 + t4 * 2;
#pragma unroll
            for (int e = 0; e < 4; ++e) {
                const int row = r0 + ((e & 2) ? 8 : 0);
                const int col = c0 + (e & 1);
                if (col < NV)
                    C[(size_t)row * NV + col] = acc[im][in][e] + bias[col];
            }
        }
    }
}

// ---------------------------------------------------------------------------
// Fused pipelined RNN scan, split barriers + depth-4 rings.
//   128 CTAs x 256 thr. Blocks 0..63: layer 0; 64..127: layer 1 (lag 1).
//   Warp w owns column jw = blk*8+w (all 4 batches); lane l covers k=l+32i.
//   Weights register-resident. Reduce: 3 butterfly shuffles -> lanes 0..3 ->
//   per-warp smem finale; lane b computes batch b (parallel tanh).
//   Epoch gating: layer0 waits bar0>=64e && bar1>=64(e-3) (slot reuse);
//                 layer1 waits bar0>=64e && bar1>=64(e-1).
// ---------------------------------------------------------------------------
__global__ __launch_bounds__(256, 1)
void scan_fused(const float* __restrict__ XW0, const float* __restrict__ Wh0,
                const float* __restrict__ Wx1, const float* __restrict__ Wh1,
                const float* __restrict__ b1,  float* __restrict__ H1) {
    __shared__ float4 hT[1024];       // [0..511]=h0, [512..1023]=h1
    __shared__ float4 sred[8][4];     // per-warp partials

    const int tid  = threadIdx.x;
    const int lane = tid & 31;
    const int warp = tid >> 5;        // 0..7
    const bool lay1 = blockIdx.x >= 64;
    const int blk = lay1 ? (int)blockIdx.x - 64 : (int)blockIdx.x;
    const int jw  = blk * 8 + warp;   // this warp's column

    // ---- preload weight column into registers ----
    float wreg[32];
    if (!lay1) {
#pragma unroll
        for (int i = 0; i < 16; ++i)
            wreg[i] = Wh0[(size_t)(lane + 32 * i) * NL + jw];
    } else {
#pragma unroll
        for (int i = 0; i < 16; ++i)
            wreg[i] = Wx1[(size_t)(lane + 32 * i) * NL + jw];
#pragma unroll
        for (int i = 16; i < 32; ++i)
            wreg[i] = Wh1[(size_t)(lane + 32 * (i - 16)) * NL + jw];
    }
    const float bias1 = (lay1 && lane < 4) ? b1[jw] : 0.f;

    unsigned* const bar0 = &g_bars[0];
    unsigned* const bar1 = &g_bars[32];
    unsigned* const barS = lay1 ? bar1 : bar0;

    const int i0 = tid, i1 = tid + 256;

    for (int e = 0; e <= NT; ++e) {
        const bool active = lay1 ? (e >= 1) : (e < NT);
        if (active) {
            // prefetch XW0 for this epoch (independent of h; hides latency)
            float xw = 0.f;
            if (!lay1 && lane < 4)
                xw = __ldg(&XW0[((size_t)lane * NT + e) * NL + jw]);

            // ---- wait for inputs (per-warp poll) ----
            if (lane == 0) {
                if (!lay1) {
                    wait_ge(bar0, 64u * (unsigned)e);
                    wait_ge(bar1, (e >= 3) ? 64u * (unsigned)(e - 3) : 0u);
                } else {
                    wait_ge(bar0, 64u * (unsigned)e);
                    wait_ge(bar1, 64u * (unsigned)(e - 1));
                }
            }
            __syncwarp();

            // ---- stage h into smem (L2-coherent loads) ----
            const int rd = (e + 3) & 3;
            hT[i0] = __ldcg(&g_h0[rd][i0]);
            hT[i1] = __ldcg(&g_h0[rd][i1]);
            if (lay1) {
                hT[512 + i0] = __ldcg(&g_h1[rd][i0]);
                hT[512 + i1] = __ldcg(&g_h1[rd][i1]);
            }
            __syncthreads();

            // ---- matvec: 4 accumulators (one per batch) ----
            float ax = 0.f, ay = 0.f, az = 0.f, aw = 0.f;
            if (!lay1) {
#pragma unroll
                for (int i = 0; i < 16; ++i) {
                    const float4 hv = hT[lane + 32 * i];
                    const float wv = wreg[i];
                    ax = fmaf(wv, hv.x, ax);
                    ay = fmaf(wv, hv.y, ay);
                    az = fmaf(wv, hv.z, az);
                    aw = fmaf(wv, hv.w, aw);
                }
            } else {
#pragma unroll
                for (int i = 0; i < 32; ++i) {
                    const float4 hv = hT[lane + 32 * i];
                    const float wv = wreg[i];
                    ax = fmaf(wv, hv.x, ax);
                    ay = fmaf(wv, hv.y, ay);
                    az = fmaf(wv, hv.z, az);
                    aw = fmaf(wv, hv.w, aw);
                }
            }
            // butterfly down to lanes 0..3
#pragma unroll
            for (int off = 16; off >= 4; off >>= 1) {
                ax += __shfl_down_sync(0xffffffffu, ax, off);
                ay += __shfl_down_sync(0xffffffffu, ay, off);
                az += __shfl_down_sync(0xffffffffu, az, off);
                aw += __shfl_down_sync(0xffffffffu, aw, off);
            }
            if (lane < 4) sred[warp][lane] = make_float4(ax, ay, az, aw);
            __syncwarp();

            if (lane < 4) {     // lane b finalizes batch b
                const float* p = (const float*)&sred[warp][0];
                const float s = p[lane] + p[4 + lane] + p[8 + lane] + p[12 + lane];
                const int wr = e & 3;
                if (!lay1) {
                    const float hn = tanhf(s + xw);
                    __stcg(&((float*)&g_h0[wr][jw])[lane], hn);
                } else {
                    const float hn = tanhf(s + bias1);
                    __stcg(&((float*)&g_h1[wr][jw])[lane], hn);
                    H1[((size_t)lane * NT + (e - 1)) * NL + jw] =
                        __uint_as_float(f2tf32(hn));   // pre-rounded for GEMM
                }
                __threadfence();  // publish before CTA arrival
            }
            __syncthreads();
            if (tid == 0)
                asm volatile("red.release.gpu.global.add.u32 [%0], %1;"
                             :: "l"(barS), "r"(1u) : "memory");
        }
    }
}

// ---------------------------------------------------------------------------
// Launch
// ---------------------------------------------------------------------------
extern "C" void kernel_launch(void* const* d_in, const int* in_sizes, int n_in,
                              void* d_out, int out_size) {
    const int*   x     = (const int*)  d_in[0];
    const float* embed = (const float*)d_in[1];
    const float* Wx0   = (const float*)d_in[2];
    const float* Wh0   = (const float*)d_in[3];
    const float* b0    = (const float*)d_in[4];
    const float* Wx1   = (const float*)d_in[5];
    const float* Wh1   = (const float*)d_in[6];
    const float* b1    = (const float*)d_in[7];
    const float* Wu    = (const float*)d_in[8];
    const float* bu    = (const float*)d_in[9];
    float* out = (float*)d_out;

    void *pA = nullptr, *pB = nullptr;
    cudaGetSymbolAddress(&pA, g_bufA);
    cudaGetSymbolAddress(&pB, g_bufB);
    float* bufA = (float*)pA;
    float* bufB = (float*)pB;

    cudaFuncSetAttribute(gemm_tf32,
                         cudaFuncAttributeMaxDynamicSharedMemorySize,
                         GEMM_SMEM);
    cudaFuncSetAttribute(gemm_unembed,
                         cudaFuncAttributeMaxDynamicSharedMemorySize,
                         UGEMM_SMEM);

    init_kernel<<<1, 256>>>();
    wu_prep<<<dim3((NVP + 255) / 256, NL), 256>>>(Wu);
    const dim3 gSmall(NL / BN, NR / BM);
    gemm_tf32<<<gSmall, GT, GEMM_SMEM>>>(embed, x, Wx0, b0, bufA, NL);
    scan_fused<<<128, 256>>>(bufA, Wh0, Wx1, Wh1, b1, bufB);
    const dim3 gBig(NVP / UBN, NR / UBM);
    gemm_unembed<<<gBig, 256, UGEMM_SMEM>>>(bufB, bu, out);
}

// round 7
// speedup vs baseline: 1.1103x; 1.1103x over previous
#include <cuda_runtime.h>
#include <cuda_bf16.h>
#include <math.h>
#include <stdint.h>

// ---------------------------------------------------------------------------
// Problem constants
// ---------------------------------------------------------------------------
#define NB   4        // batch
#define NT   1024     // time steps
#define NL   512      // latent / emb
#define NV   50257    // vocab
#define NR   (NB*NT)  // 4096 rows
#define NVP  50304    // padded vocab pitch (= 393*128, 16B-aligned rows)

// small GEMM tiling (register-staged)
#define BM   256
#define BN   128
#define BK   16
#define GT   512
#define GEMM_SMEM ((2*BM*20 + 2*BK*136)*4)

// big GEMM tiling (cp.async pipelined)
#define UBM 128
#define UBN 128
#define UBK 16
#define UST 4
#define UAS (UBM*20)
#define UBS (UBK*132)
#define UGEMM_SMEM (UST*(UAS+UBS)*4)

// ---------------------------------------------------------------------------
// Scratch (device globals — no allocation allowed)
// ---------------------------------------------------------------------------
__device__ float g_bufA[NR * NL];     // XW0 (= embed[x]@Wx0 + b0)
__device__ float g_bufB[NR * NL];     // H1, stored tf32-rounded
__device__ float g_wu[NL * NVP];      // Wu, tf32-rounded + padded
__device__ float4 g_h0[2][NL];        // depth-2 ring, layer-0 h, [k]={b0..b3}
__device__ float4 g_h1[2][NL];        // depth-2 ring, layer-1 h
__device__ unsigned g_bar;            // single joint barrier counter

// ---------------------------------------------------------------------------
// Helpers
// ---------------------------------------------------------------------------
__device__ __forceinline__ unsigned f2tf32(float f) {
    unsigned u;
    asm("cvt.rna.tf32.f32 %0, %1;" : "=r"(u) : "f"(f));
    return u;
}

__device__ __forceinline__ void mma_tf32(float c[4], const unsigned a[4],
                                         const unsigned b[2]) {
    asm volatile(
        "mma.sync.aligned.m16n8k8.row.col.f32.tf32.tf32.f32 "
        "{%0,%1,%2,%3},{%4,%5,%6,%7},{%8,%9},{%0,%1,%2,%3};"
        : "+f"(c[0]), "+f"(c[1]), "+f"(c[2]), "+f"(c[3])
        : "r"(a[0]), "r"(a[1]), "r"(a[2]), "r"(a[3]), "r"(b[0]), "r"(b[1]));
}

__device__ __forceinline__ void cp16(uint32_t dst, const void* src) {
    asm volatile("cp.async.cg.shared.global [%0], [%1], 16;\n"
                 :: "r"(dst), "l"(src));
}

// ---------------------------------------------------------------------------
// init: reset barrier + zero both h rings
// ---------------------------------------------------------------------------
__global__ void init_kernel() {
    const int tid = threadIdx.x;
    if (tid == 0) g_bar = 0u;
    float4 z = make_float4(0.f, 0.f, 0.f, 0.f);
    for (int i = tid; i < 2 * NL; i += 256) {
        ((float4*)g_h0)[i] = z;
        ((float4*)g_h1)[i] = z;
    }
}

// ---------------------------------------------------------------------------
// Wu prep: g_wu[k][n] = tf32_rna(Wu[k][n]), zero-padded to pitch NVP
// ---------------------------------------------------------------------------
__global__ void wu_prep(const float* __restrict__ Wu) {
    const int n = blockIdx.x * 256 + threadIdx.x;
    const int k = blockIdx.y;
    if (n < NVP)
        g_wu[(size_t)k * NVP + n] =
            (n < NV) ? __uint_as_float(f2tf32(Wu[(size_t)k * NV + n])) : 0.f;
}

// ---------------------------------------------------------------------------
// Small GEMM: C = A(gathered) @ B + bias (in-loop tf32 cvt). XW0 only.
// ---------------------------------------------------------------------------
__global__ __launch_bounds__(GT, 1)
void gemm_tf32(const float* __restrict__ A, const int* __restrict__ gidx,
               const float* __restrict__ B, const float* __restrict__ bias,
               float* __restrict__ C, int N) {
    extern __shared__ float sm[];
    float* As = sm;
    float* Bs = sm + 2 * BM * 20;

    const int tid  = threadIdx.x;
    const int lane = tid & 31;
    const int warp = tid >> 5;
    const int wm = warp & 3;
    const int wn = warp >> 2;
    const int g  = lane >> 2;
    const int t4 = lane & 3;

    const int rowBase = blockIdx.y * BM;
    const int nb      = blockIdx.x * BN;

    float acc[4][4][4];
#pragma unroll
    for (int a = 0; a < 4; ++a)
#pragma unroll
        for (int b = 0; b < 4; ++b)
#pragma unroll
            for (int e = 0; e < 4; ++e) acc[a][b][e] = 0.f;

    const int rl0 = tid >> 2;
    const int rl1 = rl0 + 128;
    const int c4  = tid & 3;
    const float* arow0;
    const float* arow1;
    {
        const int r0 = rowBase + rl0;
        const int r1 = rowBase + rl1;
        arow0 = A + (size_t)(gidx ? gidx[r0] : r0) * NL;
        arow1 = A + (size_t)(gidx ? gidx[r1] : r1) * NL;
    }

    float4 pa0, pa1;
    float  pb[4];
    pa0 = *(const float4*)(arow0 + c4 * 4);
    pa1 = *(const float4*)(arow1 + c4 * 4);
#pragma unroll
    for (int i = 0; i < 4; ++i) {
        const int id  = tid + i * GT;
        const int kr  = id >> 7;
        const int col = id & 127;
        const int n   = nb + col;
        pb[i] = (n < N) ? B[(size_t)kr * N + n] : 0.f;
    }

    int w = 0;
    for (int kb = 0; kb < NL; kb += BK) {
        {
            float4 w0, w1;
            w0.x = __uint_as_float(f2tf32(pa0.x));
            w0.y = __uint_as_float(f2tf32(pa0.y));
            w0.z = __uint_as_float(f2tf32(pa0.z));
            w0.w = __uint_as_float(f2tf32(pa0.w));
            w1.x = __uint_as_float(f2tf32(pa1.x));
            w1.y = __uint_as_float(f2tf32(pa1.y));
            w1.z = __uint_as_float(f2tf32(pa1.z));
            w1.w = __uint_as_float(f2tf32(pa1.w));
            *(float4*)&As[w * (BM * 20) + rl0 * 20 + c4 * 4] = w0;
            *(float4*)&As[w * (BM * 20) + rl1 * 20 + c4 * 4] = w1;
#pragma unroll
            for (int i = 0; i < 4; ++i) {
                const int id  = tid + i * GT;
                const int kr  = id >> 7;
                const int col = id & 127;
                Bs[w * (BK * 136) + kr * 136 + col] =
                    __uint_as_float(f2tf32(pb[i]));
            }
        }
        __syncthreads();

        if (kb + BK < NL) {
            pa0 = *(const float4*)(arow0 + kb + BK + c4 * 4);
            pa1 = *(const float4*)(arow1 + kb + BK + c4 * 4);
#pragma unroll
            for (int i = 0; i < 4; ++i) {
                const int id  = tid + i * GT;
                const int kr  = id >> 7;
                const int col = id & 127;
                const int n   = nb + col;
                pb[i] = (n < N) ? B[(size_t)(kb + BK + kr) * N + n] : 0.f;
            }
        }

        const float* Aw = &As[w * (BM * 20)];
        const float* Bw = &Bs[w * (BK * 136)];
#pragma unroll
        for (int ks = 0; ks < BK; ks += 8) {
            unsigned af[4][4], bf[4][2];
#pragma unroll
            for (int im = 0; im < 4; ++im) {
                const int m0 = wm * 64 + im * 16;
                const float* a0 = Aw + (m0 + g) * 20 + ks + t4;
                const float* a1 = Aw + (m0 + g + 8) * 20 + ks + t4;
                af[im][0] = __float_as_uint(a0[0]);
                af[im][1] = __float_as_uint(a1[0]);
                af[im][2] = __float_as_uint(a0[4]);
                af[im][3] = __float_as_uint(a1[4]);
            }
#pragma unroll
            for (int in = 0; in < 4; ++in) {
                const int n0 = wn * 32 + in * 8;
                bf[in][0] = __float_as_uint(Bw[(ks + t4) * 136 + n0 + g]);
                bf[in][1] = __float_as_uint(Bw[(ks + t4 + 4) * 136 + n0 + g]);
            }
#pragma unroll
            for (int im = 0; im < 4; ++im)
#pragma unroll
                for (int in = 0; in < 4; ++in)
                    mma_tf32(acc[im][in], af[im], bf[in]);
        }
        w ^= 1;
    }

#pragma unroll
    for (int im = 0; im < 4; ++im) {
        const int r0 = rowBase + wm * 64 + im * 16 + g;
#pragma unroll
        for (int in = 0; in < 4; ++in) {
            const int c0 = nb + wn * 32 + in * 8 + t4 * 2;
#pragma unroll
            for (int e = 0; e < 4; ++e) {
                const int row = r0 + ((e & 2) ? 8 : 0);
                const int col = c0 + (e & 1);
                if (col < N)
                    C[(size_t)row * N + col] = acc[im][in][e] + bias[col];
            }
        }
    }
}

// ---------------------------------------------------------------------------
// Big unembed GEMM: out = H1(tf32 bits) @ g_wu + bu. 128x128x16, cp.async x4.
// ---------------------------------------------------------------------------
__global__ __launch_bounds__(256, 2)
void gemm_unembed(const float* __restrict__ A, const float* __restrict__ bias,
                  float* __restrict__ C) {
    extern __shared__ float sm[];
    const uint32_t smem_u32 = (uint32_t)__cvta_generic_to_shared(sm);

    const int tid  = threadIdx.x;
    const int lane = tid & 31;
    const int warp = tid >> 5;
    const int wm = warp & 1;
    const int wn = warp >> 1;
    const int g  = lane >> 2;
    const int t4 = lane & 3;

    const int rowBase = blockIdx.y * UBM;
    const int nb      = blockIdx.x * UBN;

    float acc[4][4][4];
#pragma unroll
    for (int a = 0; a < 4; ++a)
#pragma unroll
        for (int b = 0; b < 4; ++b)
#pragma unroll
            for (int e = 0; e < 4; ++e) acc[a][b][e] = 0.f;

    const int arow = tid >> 2;
    const int ac4  = tid & 3;
    const float* aptr0 = A + (size_t)(rowBase + arow) * NL + ac4 * 4;
    const float* aptr1 = A + (size_t)(rowBase + arow + 64) * NL + ac4 * 4;
    const int bkr0 = tid >> 5;
    const int bc0  = tid & 31;
    const float* bptr0 = g_wu + (size_t)bkr0 * NVP + nb + bc0 * 4;
    const float* bptr1 = g_wu + (size_t)(bkr0 + 8) * NVP + nb + bc0 * 4;

    const uint32_t adst0 = smem_u32 + (arow * 20 + ac4 * 4) * 4;
    const uint32_t adst1 = smem_u32 + ((arow + 64) * 20 + ac4 * 4) * 4;
    const uint32_t bdst0 = smem_u32 + (UST * UAS + bkr0 * 132 + bc0 * 4) * 4;
    const uint32_t bdst1 = smem_u32 + (UST * UAS + (bkr0 + 8) * 132 + bc0 * 4) * 4;

    const int NKT = NL / UBK;

#pragma unroll
    for (int s = 0; s < UST - 1; ++s) {
        const int kb = s * UBK;
        cp16(adst0 + s * UAS * 4, aptr0 + kb);
        cp16(adst1 + s * UAS * 4, aptr1 + kb);
        cp16(bdst0 + s * UBS * 4, bptr0 + (size_t)kb * NVP);
        cp16(bdst1 + s * UBS * 4, bptr1 + (size_t)kb * NVP);
        asm volatile("cp.async.commit_group;\n" ::);
    }

    for (int kt = 0; kt < NKT; ++kt) {
        asm volatile("cp.async.wait_group 2;\n" ::);
        __syncthreads();

        if (kt + UST - 1 < NKT) {
            const int s  = (kt + UST - 1) & (UST - 1);
            const int kb = (kt + UST - 1) * UBK;
            cp16(adst0 + s * UAS * 4, aptr0 + kb);
            cp16(adst1 + s * UAS * 4, aptr1 + kb);
            cp16(bdst0 + s * UBS * 4, bptr0 + (size_t)kb * NVP);
            cp16(bdst1 + s * UBS * 4, bptr1 + (size_t)kb * NVP);
        }
        asm volatile("cp.async.commit_group;\n" ::);

        const float* Aw = sm + (kt & (UST - 1)) * UAS;
        const float* Bw = sm + UST * UAS + (kt & (UST - 1)) * UBS;
#pragma unroll
        for (int ks = 0; ks < UBK; ks += 8) {
            unsigned af[4][4], bf[4][2];
#pragma unroll
            for (int im = 0; im < 4; ++im) {
                const int m0 = wm * 64 + im * 16;
                const float* a0 = Aw + (m0 + g) * 20 + ks + t4;
                const float* a1 = Aw + (m0 + g + 8) * 20 + ks + t4;
                af[im][0] = __float_as_uint(a0[0]);
                af[im][1] = __float_as_uint(a1[0]);
                af[im][2] = __float_as_uint(a0[4]);
                af[im][3] = __float_as_uint(a1[4]);
            }
#pragma unroll
            for (int in = 0; in < 4; ++in) {
                const int n0 = wn * 32 + in * 8;
                bf[in][0] = __float_as_uint(Bw[(ks + t4) * 132 + n0 + g]);
                bf[in][1] = __float_as_uint(Bw[(ks + t4 + 4) * 132 + n0 + g]);
            }
#pragma unroll
            for (int im = 0; im < 4; ++im)
#pragma unroll
                for (int in = 0; in < 4; ++in)
                    mma_tf32(acc[im][in], af[im], bf[in]);
        }
    }

#pragma unroll
    for (int im = 0; im < 4; ++im) {
        const int r0 = rowBase + wm * 64 + im * 16 + g;
#pragma unroll
        for (int in = 0; in < 4; ++in) {
            const int c0 = nb + wn * 32 + in * 8 + t4 * 2;
#pragma unroll
            for (int e = 0; e < 4; ++e) {
                const int row = r0 + ((e & 2) ? 8 : 0);
                const int col = c0 + (e & 1);
                if (col < NV)
                    C[(size_t)row * NV + col] = acc[im][in][e] + bias[col];
            }
        }
    }
}

// ---------------------------------------------------------------------------
// Fused pipelined RNN scan — 64 CTAs, BOTH layers per CTA, 1 joint barrier.
//   Epoch e: layer0 computes h0_e   = tanh(XW0[:,e,:] + h0_{e-1}@Wh0)
//            layer1 computes h1_{e-1}= tanh(h0_{e-1}@Wx1 + h1_{e-2}@Wh1 + b1)
//   Warp w owns column jw = blk*8+w for BOTH layers; lane l covers k=l+32i.
//   Sync: ONE poller/CTA (ld.acquire) -> __syncthreads; writers -> syncthreads
//   -> tid0 red.release (PTX-cumulative release chain; no threadfence).
//   Depth-2 rings safe: the joint barrier keeps all CTAs within one epoch —
//   a CTA enters e+1 (overwriting slot (e+1)&1) only after every CTA finished
//   ALL epoch-e reads (reads precede arrivals).
// ---------------------------------------------------------------------------
__global__ __launch_bounds__(256, 1)
void scan_fused(const float* __restrict__ XW0, const float* __restrict__ Wh0,
                const float* __restrict__ Wx1, const float* __restrict__ Wh1,
                const float* __restrict__ b1,  float* __restrict__ H1) {
    __shared__ float4 hT0[512];       // h0_{e-1}
    __shared__ float4 hT1[512];       // h1_{e-2}
    __shared__ float4 sred0[8][4];    // layer-0 per-warp partials
    __shared__ float4 sred1[8][4];    // layer-1 per-warp partials

    const int tid  = threadIdx.x;
    const int lane = tid & 31;
    const int warp = tid >> 5;        // 0..7
    const int blk  = blockIdx.x;      // 0..63
    const int jw   = blk * 8 + warp;  // this warp's column (both layers)

    // ---- preload weight columns into registers (48 floats) ----
    float w0[16], w1x[16], w1h[16];
#pragma unroll
    for (int i = 0; i < 16; ++i) {
        const size_t k = (size_t)(lane + 32 * i) * NL + jw;
        w0[i]  = Wh0[k];
        w1x[i] = Wx1[k];
        w1h[i] = Wh1[k];
    }
    const float bias1 = (lane >= 4 && lane < 8) ? b1[jw] : 0.f;

    unsigned* const barp = &g_bar;
    const int i0 = tid, i1 = tid + 256;

    for (int e = 0; e <= NT; ++e) {
        const bool do0 = (e < NT);
        const bool do1 = (e >= 1);

        // prefetch XW0 for this epoch (independent of barrier/h)
        float xw = 0.f;
        if (do0 && lane < 4)
            xw = __ldg(&XW0[((size_t)lane * NT + e) * NL + jw]);

        // ---- wait: single poller per CTA ----
        if (tid == 0 && e > 0) {
            const unsigned tgt = 64u * (unsigned)e;
            unsigned v;
            do {
                asm volatile("ld.acquire.gpu.global.u32 %0, [%1];"
                             : "=r"(v) : "l"(barp) : "memory");
            } while (v < tgt);
        }
        __syncthreads();

        // ---- stage h states into smem (L2-coherent) ----
        // h0_{e-1}: slot (e-1)&1 == (e+1)&1 ; h1_{e-2}: slot (e-2)&1 == e&1
        hT0[i0] = __ldcg(&g_h0[(e + 1) & 1][i0]);
        hT0[i1] = __ldcg(&g_h0[(e + 1) & 1][i1]);
        if (do1) {
            hT1[i0] = __ldcg(&g_h1[e & 1][i0]);
            hT1[i1] = __ldcg(&g_h1[e & 1][i1]);
        }
        __syncthreads();

        // ---- matvecs: layer0 (K=512) + layer1 (K=1024), fused hT0 reads ----
        float ax = 0.f, ay = 0.f, az = 0.f, aw = 0.f;   // layer0
        float bx = 0.f, by = 0.f, bz = 0.f, bw = 0.f;   // layer1
#pragma unroll
        for (int i = 0; i < 16; ++i) {
            const float4 hv = hT0[lane + 32 * i];
            const float wa = w0[i];
            const float wb = w1x[i];
            ax = fmaf(wa, hv.x, ax);
            ay = fmaf(wa, hv.y, ay);
            az = fmaf(wa, hv.z, az);
            aw = fmaf(wa, hv.w, aw);
            bx = fmaf(wb, hv.x, bx);
            by = fmaf(wb, hv.y, by);
            bz = fmaf(wb, hv.z, bz);
            bw = fmaf(wb, hv.w, bw);
        }
        if (do1) {
#pragma unroll
            for (int i = 0; i < 16; ++i) {
                const float4 hv = hT1[lane + 32 * i];
                const float wb = w1h[i];
                bx = fmaf(wb, hv.x, bx);
                by = fmaf(wb, hv.y, by);
                bz = fmaf(wb, hv.z, bz);
                bw = fmaf(wb, hv.w, bw);
            }
        }

        // ---- butterfly to lanes 0..3 (8 independent chains pipeline) ----
#pragma unroll
        for (int off = 16; off >= 4; off >>= 1) {
            ax += __shfl_down_sync(0xffffffffu, ax, off);
            ay += __shfl_down_sync(0xffffffffu, ay, off);
            az += __shfl_down_sync(0xffffffffu, az, off);
            aw += __shfl_down_sync(0xffffffffu, aw, off);
            bx += __shfl_down_sync(0xffffffffu, bx, off);
            by += __shfl_down_sync(0xffffffffu, by, off);
            bz += __shfl_down_sync(0xffffffffu, bz, off);
            bw += __shfl_down_sync(0xffffffffu, bw, off);
        }
        if (lane < 4) {
            sred0[warp][lane] = make_float4(ax, ay, az, aw);
            sred1[warp][lane] = make_float4(bx, by, bz, bw);
        }
        __syncwarp();

        // ---- parallel finale: lanes 0..3 layer0, lanes 4..7 layer1 ----
        if (do0 && lane < 4) {
            const float* p = (const float*)&sred0[warp][0];
            const float s = p[lane] + p[4 + lane] + p[8 + lane] + p[12 + lane];
            const float hn = tanhf(s + xw);
            __stcg(&((float*)&g_h0[e & 1][jw])[lane], hn);   // h0_e
        }
        if (do1 && lane >= 4 && lane < 8) {
            const int b = lane - 4;
            const float* p = (const float*)&sred1[warp][0];
            const float s = p[b] + p[4 + b] + p[8 + b] + p[12 + b];
            const float hn = tanhf(s + bias1);
            __stcg(&((float*)&g_h1[(e + 1) & 1][jw])[b], hn); // h1_{e-1}
            H1[((size_t)b * NT + (e - 1)) * NL + jw] =
                __uint_as_float(f2tf32(hn));   // pre-rounded for GEMM
        }

        if (e < NT) {
            __syncthreads();   // CTA-wide HB edge: writes -> tid0's release
            if (tid == 0)
                asm volatile("red.release.gpu.global.add.u32 [%0], %1;"
                             :: "l"(barp), "r"(1u) : "memory");
        }
    }
}

// ---------------------------------------------------------------------------
// Launch
// ---------------------------------------------------------------------------
extern "C" void kernel_launch(void* const* d_in, const int* in_sizes, int n_in,
                              void* d_out, int out_size) {
    const int*   x     = (const int*)  d_in[0];
    const float* embed = (const float*)d_in[1];
    const float* Wx0   = (const float*)d_in[2];
    const float* Wh0   = (const float*)d_in[3];
    const float* b0    = (const float*)d_in[4];
    const float* Wx1   = (const float*)d_in[5];
    const float* Wh1   = (const float*)d_in[6];
    const float* b1    = (const float*)d_in[7];
    const float* Wu    = (const float*)d_in[8];
    const float* bu    = (const float*)d_in[9];
    float* out = (float*)d_out;

    void *pA = nullptr, *pB = nullptr;
    cudaGetSymbolAddress(&pA, g_bufA);
    cudaGetSymbolAddress(&pB, g_bufB);
    float* bufA = (float*)pA;
    float* bufB = (float*)pB;

    cudaFuncSetAttribute(gemm_tf32,
                         cudaFuncAttributeMaxDynamicSharedMemorySize,
                         GEMM_SMEM);
    cudaFuncSetAttribute(gemm_unembed,
                         cudaFuncAttributeMaxDynamicSharedMemorySize,
                         UGEMM_SMEM);

    init_kernel<<<1, 256>>>();
    wu_prep<<<dim3((NVP + 255) / 256, NL), 256>>>(Wu);
    const dim3 gSmall(NL / BN, NR / BM);
    gemm_tf32<<<gSmall, GT, GEMM_SMEM>>>(embed, x, Wx0, b0, bufA, NL);
    scan_fused<<<64, 256>>>(bufA, Wh0, Wx1, Wh1, b1, bufB);
    const dim3 gBig(NVP / UBN, NR / UBM);
    gemm_unembed<<<gBig, 256, UGEMM_SMEM>>>(bufB, bu, out);
}